// round 1
// baseline (speedup 1.0000x reference)
#include <cuda_runtime.h>
#include <math.h>

#define NPTS 16384
#define KNN 16
#define SEQ 8
#define PARTS 8
#define QPB 32
#define BLOCK 256
#define TILE 1024
#define NBLK_KNN (NPTS / QPB)          /* 512 */
#define NBLK_LOSS ((SEQ * NPTS) / 256) /* 512 */

// Scratch (no allocations allowed)
__device__ int   g_idx[NPTS * KNN];
__device__ float g_partials[NBLK_LOSS];
__device__ float g_wsum;

// ---------------------------------------------------------------------------
// kNN: each block handles 32 queries; each query owned by 8 threads that
// partition candidates by (j mod 8). Candidate tiles staged in smem as float4.
// Per-thread register-resident sorted top-16; merged per query via smem.
// ---------------------------------------------------------------------------
__global__ __launch_bounds__(BLOCK) void knn_kernel(const float* __restrict__ pc) {
    // Max of: tile (TILE float4 = 4096 floats) and merge area (2 * 32*129)
    __shared__ __align__(16) float SB[2 * QPB * 129];

    const int t    = threadIdx.x;
    const int ql   = t >> 3;   // local query 0..31
    const int part = t & 7;    // candidate partition 0..7
    const int q    = blockIdx.x * QPB + ql;

    const float qx = pc[q * 3 + 0];
    const float qy = pc[q * 3 + 1];
    const float qz = pc[q * 3 + 2];

    float d[KNN];
    int   id[KNN];
#pragma unroll
    for (int k = 0; k < KNN; k++) { d[k] = 3.0e38f; id[k] = 0; }

    float4* s4 = (float4*)SB;

    for (int base = 0; base < NPTS; base += TILE) {
        __syncthreads();
        // cooperative tile fill: TILE points * 3 comps -> padded float4 slots
        for (int u = t; u < TILE * 3; u += BLOCK) {
            int j = u / 3;
            int c = u - j * 3;
            SB[j * 4 + c] = pc[base * 3 + u];
        }
        __syncthreads();

#pragma unroll 4
        for (int jj = part; jj < TILE; jj += PARTS) {
            float4 c4 = s4[jj];
            float dx = qx - c4.x;
            float dy = qy - c4.y;
            float dz = qz - c4.z;
            float d2 = dx * dx;
            d2 = fmaf(dy, dy, d2);
            d2 = fmaf(dz, dz, d2);
            if (d2 < d[KNN - 1]) {
                float v   = d2;
                int   vid = base + jj;
                bool placed = false;
#pragma unroll
                for (int s = KNN - 1; s > 0; --s) {
                    if (!placed) {
                        if (d[s - 1] > v) { d[s] = d[s - 1]; id[s] = id[s - 1]; }
                        else              { d[s] = v;        id[s] = vid; placed = true; }
                    }
                }
                if (!placed) { d[0] = v; id[0] = vid; }
            }
        }
    }

    __syncthreads();
    // dump partial lists: pitch 129 floats per query -> conflict-free merge reads
    float* md = SB;
    int*   mi = (int*)(SB + QPB * 129);
    const int off = ql * 129 + part * KNN;
#pragma unroll
    for (int k = 0; k < KNN; k++) { md[off + k] = d[k]; mi[off + k] = id[k]; }
    __syncthreads();

    if (t < QPB) {
        const int qq   = blockIdx.x * QPB + t;
        const int boff = t * 129;
        float bd[KNN];
        int   bi[KNN];
#pragma unroll
        for (int k = 0; k < KNN; k++) { bd[k] = md[boff + k]; bi[k] = mi[boff + k]; }

        for (int p = 1; p < PARTS; p++) {
            const int po = boff + p * KNN;
            for (int k = 0; k < KNN; k++) {
                float v = md[po + k];
                if (v >= bd[KNN - 1]) break;  // sorted sublist -> done with this partition
                int vid = mi[po + k];
                bool placed = false;
#pragma unroll
                for (int s = KNN - 1; s > 0; --s) {
                    if (!placed) {
                        if (bd[s - 1] > v) { bd[s] = bd[s - 1]; bi[s] = bi[s - 1]; }
                        else               { bd[s] = v;         bi[s] = vid; placed = true; }
                    }
                }
                if (!placed) { bd[0] = v; bi[0] = vid; }
            }
        }

        // radius filter: dist > 1.0  <=>  d2 > 1.0 ; nearest (bd[0]=0) is self
        const int self = bi[0];
#pragma unroll
        for (int k = 0; k < KNN; k++)
            g_idx[qq * KNN + k] = (bd[k] > 1.0f) ? self : bi[k];
    }
}

// ---------------------------------------------------------------------------
// wsum (single block, deterministic tree reduce)
// ---------------------------------------------------------------------------
__global__ void wsum_kernel(const float* __restrict__ w) {
    __shared__ float red[256];
    float a = 0.0f;
    for (int i = threadIdx.x; i < NPTS; i += 256) a += w[i];
    red[threadIdx.x] = a;
    __syncthreads();
    for (int st = 128; st > 0; st >>= 1) {
        if (threadIdx.x < st) red[threadIdx.x] += red[threadIdx.x + st];
        __syncthreads();
    }
    if (threadIdx.x == 0) g_wsum = red[0];
}

// ---------------------------------------------------------------------------
// Loss: one thread per (seq, point); 16 neighbor-flow gathers (L2 resident).
// Fixed-order block reduce -> per-block partials (fully deterministic).
// ---------------------------------------------------------------------------
__global__ __launch_bounds__(256) void loss_kernel(const float* __restrict__ flow,
                                                   const float* __restrict__ w) {
    const int gid = blockIdx.x * 256 + threadIdx.x;  // 0 .. SEQ*NPTS-1
    const int s   = gid / NPTS;
    const int i   = gid - s * NPTS;
    const float* f = flow + (size_t)s * NPTS * 3;

    const float fx = f[i * 3 + 0];
    const float fy = f[i * 3 + 1];
    const float fz = f[i * 3 + 2];

    float acc = 0.0f;
#pragma unroll
    for (int k = 0; k < KNN; k++) {
        int j = g_idx[i * KNN + k];
        float dx = fx - f[j * 3 + 0];
        float dy = fy - f[j * 3 + 1];
        float dz = fz - f[j * 3 + 2];
        float sq = dx * dx;
        sq = fmaf(dy, dy, sq);
        sq = fmaf(dz, dz, sq);
        acc += (sq > 0.0f) ? sqrtf(sq) : 0.0f;
    }
    float val = w[i] * (acc * (1.0f / KNN));

    __shared__ float red[256];
    red[threadIdx.x] = val;
    __syncthreads();
    for (int st = 128; st > 0; st >>= 1) {
        if (threadIdx.x < st) red[threadIdx.x] += red[threadIdx.x + st];
        __syncthreads();
    }
    if (threadIdx.x == 0) g_partials[blockIdx.x] = red[0];
}

// ---------------------------------------------------------------------------
// Final: deterministic reduce of 512 partials, apply wsum + seq mean.
// ---------------------------------------------------------------------------
__global__ void final_kernel(float* __restrict__ out) {
    __shared__ float red[512];
    red[threadIdx.x] = g_partials[threadIdx.x];
    __syncthreads();
    for (int st = 256; st > 0; st >>= 1) {
        if (threadIdx.x < st) red[threadIdx.x] += red[threadIdx.x + st];
        __syncthreads();
    }
    if (threadIdx.x == 0) {
        float tot = red[0];
        float ws  = g_wsum;
        float ls  = (ws > 0.0f) ? (tot / ws) : tot;
        out[0] = ls * (1.0f / SEQ);
    }
}

extern "C" void kernel_launch(void* const* d_in, const int* in_sizes, int n_in,
                              void* d_out, int out_size) {
    const float* pc   = (const float*)d_in[0];  // (1, 16384, 3)
    const float* flow = (const float*)d_in[1];  // (8, 16384, 3)
    const float* w    = (const float*)d_in[2];  // (16384,)
    float* out = (float*)d_out;

    knn_kernel<<<NBLK_KNN, BLOCK>>>(pc);
    wsum_kernel<<<1, 256>>>(w);
    loss_kernel<<<NBLK_LOSS, 256>>>(flow, w);
    final_kernel<<<1, 512>>>(out);
}

// round 2
// speedup vs baseline: 1.8849x; 1.8849x over previous
#include <cuda_runtime.h>
#include <math.h>

#define NPTS   16384
#define KNN    16
#define SEQ    8
#define NCELLS 32768      /* 32^3 morton cells */
#define NTILES 128        /* NPTS / TPT */
#define TPT    128        /* points per tile */
#define NBLK_LOSS 512

// ---------------- device scratch (no allocations allowed) ------------------
__device__ float4 g_sorted[NPTS];          // xyz + orig idx (bit-cast)
__device__ int    g_key[NPTS];
__device__ int    g_cnt[NCELLS];
__device__ int    g_cur[NCELLS];
__device__ float4 g_blo[NTILES];
__device__ float4 g_bhi[NTILES];
__device__ int    g_idx[NPTS * KNN];
__device__ float  g_partials[NBLK_LOSS];
__device__ float  g_wsum;

// 5-bit -> every-3rd-bit spread for morton interleave
__device__ __forceinline__ unsigned mpart5(unsigned x) {
    x &= 31u;
    x = (x | (x << 8)) & 0x100Fu;
    x = (x | (x << 4)) & 0x10C3u;
    x = (x | (x << 2)) & 0x1249u;
    return x;
}

// ---------------------------------------------------------------------------
__global__ void zero_kernel() {
    int i = blockIdx.x * 256 + threadIdx.x;
    if (i < NCELLS) g_cnt[i] = 0;
}

__global__ void count_kernel(const float* __restrict__ pc) {
    int i = blockIdx.x * 256 + threadIdx.x;
    float x = pc[i * 3 + 0], y = pc[i * 3 + 1], z = pc[i * 3 + 2];
    int cx = min(31, max(0, (int)floorf((x + 5.0f) * 3.2f)));
    int cy = min(31, max(0, (int)floorf((y + 5.0f) * 3.2f)));
    int cz = min(31, max(0, (int)floorf((z + 5.0f) * 3.2f)));
    int key = (int)(mpart5(cx) | (mpart5(cy) << 1) | (mpart5(cz) << 2));
    g_key[i] = key;
    atomicAdd(&g_cnt[key], 1);
}

// single block, 1024 threads: exclusive scan of 32768 counts
__global__ void scan_kernel() {
    __shared__ int s[1024];
    int t = threadIdx.x;
    int base = t * 32;
    int loc[32];
    int sum = 0;
#pragma unroll
    for (int k = 0; k < 32; k++) { loc[k] = g_cnt[base + k]; sum += loc[k]; }
    s[t] = sum;
    __syncthreads();
    for (int off = 1; off < 1024; off <<= 1) {
        int v = (t >= off) ? s[t - off] : 0;
        __syncthreads();
        s[t] += v;
        __syncthreads();
    }
    int run = s[t] - sum;  // exclusive prefix of this thread's chunk
#pragma unroll
    for (int k = 0; k < 32; k++) { g_cur[base + k] = run; run += loc[k]; }
}

__global__ void scatter_kernel(const float* __restrict__ pc) {
    int i = blockIdx.x * 256 + threadIdx.x;
    int pos = atomicAdd(&g_cur[g_key[i]], 1);
    g_sorted[pos] = make_float4(pc[i * 3 + 0], pc[i * 3 + 1], pc[i * 3 + 2],
                                __int_as_float(i));
}

// single block, 128 threads: per-tile bounding boxes
__global__ void bbox_kernel() {
    int t = threadIdx.x;
    float lx = 3e38f, ly = 3e38f, lz = 3e38f;
    float hx = -3e38f, hy = -3e38f, hz = -3e38f;
    const float4* p = g_sorted + t * TPT;
    for (int j = 0; j < TPT; j++) {
        float4 c = p[j];
        lx = fminf(lx, c.x); hx = fmaxf(hx, c.x);
        ly = fminf(ly, c.y); hy = fmaxf(hy, c.y);
        lz = fminf(lz, c.z); hz = fmaxf(hz, c.z);
    }
    g_blo[t] = make_float4(lx, ly, lz, 0.0f);
    g_bhi[t] = make_float4(hx, hy, hz, 0.0f);
}

// ---------------------------------------------------------------------------
// Pruned kNN: 1 thread per query, 1 warp per 32 co-located (sorted) queries.
// Visit tiles in expanding order from own tile; skip tiles whose bbox
// min-dist^2 exceeds the current 16th-best. Tie-break on index makes the
// result independent of the (atomic-order-dependent) within-cell sort order
// and matches jax.lax.top_k's lowest-index-first tie semantics.
// ---------------------------------------------------------------------------
__global__ __launch_bounds__(64) void knn_kernel() {
    const int gid = blockIdx.x * 64 + threadIdx.x;   // sorted query index
    const float4 q = g_sorted[gid];
    const int qidx = __float_as_int(q.w);
    const int tile0 = blockIdx.x >> 1;               // uniform: block spans half a tile

    float d[KNN];
    int   id[KNN];
#pragma unroll
    for (int k = 0; k < KNN; k++) { d[k] = 3.0e38f; id[k] = 0x7FFFFFFF; }

    for (int s = 0; s < 2 * NTILES; s++) {
        int half = (s + 1) >> 1;
        int t = (s & 1) ? (tile0 - half) : (tile0 + half);
        if ((unsigned)t >= NTILES) continue;         // uniform branch

        float4 lo = g_blo[t];
        float4 hi = g_bhi[t];
        float ddx = fmaxf(fmaxf(lo.x - q.x, q.x - hi.x), 0.0f);
        float ddy = fmaxf(fmaxf(lo.y - q.y, q.y - hi.y), 0.0f);
        float ddz = fmaxf(fmaxf(lo.z - q.z, q.z - hi.z), 0.0f);
        float mind2 = fmaf(ddx, ddx, fmaf(ddy, ddy, ddz * ddz));
        bool need = (mind2 <= d[KNN - 1]);

        if (__ballot_sync(0xFFFFFFFFu, need) == 0u) continue;

        if (need) {
            const float4* cp = g_sorted + t * TPT;
#pragma unroll 4
            for (int j = 0; j < TPT; j++) {
                float4 c = cp[j];
                float dx = q.x - c.x;
                float dy = q.y - c.y;
                float dz = q.z - c.z;
                float d2 = fmaf(dx, dx, fmaf(dy, dy, dz * dz));
                int cidx = __float_as_int(c.w);
                if (d2 < d[KNN - 1] ||
                    (d2 == d[KNN - 1] && cidx < id[KNN - 1])) {
                    bool placed = false;
#pragma unroll
                    for (int s2 = KNN - 1; s2 > 0; --s2) {
                        if (!placed) {
                            bool mv = (d[s2 - 1] > d2) ||
                                      (d[s2 - 1] == d2 && id[s2 - 1] > cidx);
                            if (mv) { d[s2] = d[s2 - 1]; id[s2] = id[s2 - 1]; }
                            else    { d[s2] = d2; id[s2] = cidx; placed = true; }
                        }
                    }
                    if (!placed) { d[0] = d2; id[0] = cidx; }
                }
            }
        }
    }

    // radius filter: dist > 1  <=>  d2 > 1 ; nearest (d[0]=0) is self
    const int self = id[0];
#pragma unroll
    for (int k = 0; k < KNN; k++)
        g_idx[qidx * KNN + k] = (d[k] > 1.0f) ? self : id[k];
}

// ---------------------------------------------------------------------------
__global__ void wsum_kernel(const float* __restrict__ w) {
    __shared__ float red[256];
    float a = 0.0f;
    for (int i = threadIdx.x; i < NPTS; i += 256) a += w[i];
    red[threadIdx.x] = a;
    __syncthreads();
    for (int st = 128; st > 0; st >>= 1) {
        if (threadIdx.x < st) red[threadIdx.x] += red[threadIdx.x + st];
        __syncthreads();
    }
    if (threadIdx.x == 0) g_wsum = red[0];
}

__global__ __launch_bounds__(256) void loss_kernel(const float* __restrict__ flow,
                                                   const float* __restrict__ w) {
    const int gid = blockIdx.x * 256 + threadIdx.x;  // 0 .. SEQ*NPTS-1
    const int s   = gid / NPTS;
    const int i   = gid - s * NPTS;
    const float* f = flow + (size_t)s * NPTS * 3;

    const float fx = f[i * 3 + 0];
    const float fy = f[i * 3 + 1];
    const float fz = f[i * 3 + 2];

    float acc = 0.0f;
#pragma unroll
    for (int k = 0; k < KNN; k++) {
        int j = g_idx[i * KNN + k];
        float dx = fx - f[j * 3 + 0];
        float dy = fy - f[j * 3 + 1];
        float dz = fz - f[j * 3 + 2];
        float sq = dx * dx;
        sq = fmaf(dy, dy, sq);
        sq = fmaf(dz, dz, sq);
        acc += (sq > 0.0f) ? sqrtf(sq) : 0.0f;
    }
    float val = w[i] * (acc * (1.0f / KNN));

    __shared__ float red[256];
    red[threadIdx.x] = val;
    __syncthreads();
    for (int st = 128; st > 0; st >>= 1) {
        if (threadIdx.x < st) red[threadIdx.x] += red[threadIdx.x + st];
        __syncthreads();
    }
    if (threadIdx.x == 0) g_partials[blockIdx.x] = red[0];
}

__global__ void final_kernel(float* __restrict__ out) {
    __shared__ float red[512];
    red[threadIdx.x] = g_partials[threadIdx.x];
    __syncthreads();
    for (int st = 256; st > 0; st >>= 1) {
        if (threadIdx.x < st) red[threadIdx.x] += red[threadIdx.x + st];
        __syncthreads();
    }
    if (threadIdx.x == 0) {
        float tot = red[0];
        float ws  = g_wsum;
        float ls  = (ws > 0.0f) ? (tot / ws) : tot;
        out[0] = ls * (1.0f / SEQ);
    }
}

// ---------------------------------------------------------------------------
extern "C" void kernel_launch(void* const* d_in, const int* in_sizes, int n_in,
                              void* d_out, int out_size) {
    const float* pc   = (const float*)d_in[0];  // (1, 16384, 3)
    const float* flow = (const float*)d_in[1];  // (8, 16384, 3)
    const float* w    = (const float*)d_in[2];  // (16384,)
    float* out = (float*)d_out;

    zero_kernel<<<NCELLS / 256, 256>>>();
    count_kernel<<<NPTS / 256, 256>>>(pc);
    scan_kernel<<<1, 1024>>>();
    scatter_kernel<<<NPTS / 256, 256>>>(pc);
    bbox_kernel<<<1, NTILES>>>();
    knn_kernel<<<NPTS / 64, 64>>>();
    wsum_kernel<<<1, 256>>>(w);
    loss_kernel<<<NBLK_LOSS, 256>>>(flow, w);
    final_kernel<<<1, 512>>>(out);
}

// round 3
// speedup vs baseline: 3.3542x; 1.7795x over previous
#include <cuda_runtime.h>
#include <math.h>

#define NPTS   16384
#define KNN    16
#define SEQ    8
#define NCELLS 32768      /* 32^3 morton cells */
#define NTILES 128        /* NPTS / TPT */
#define TPT    128        /* points per tile */
#define PARTS  4          /* threads per query in knn */
#define QPB    64         /* queries per knn block */
#define NBLK_LOSS 512

// ---------------- device scratch (no allocations allowed) ------------------
__device__ float4 g_sorted[NPTS];          // xyz + orig idx (bit-cast)
__device__ int    g_key[NPTS];
__device__ int    g_cnt[NCELLS];
__device__ int    g_cur[NCELLS];
__device__ float4 g_blo[NTILES];
__device__ float4 g_bhi[NTILES];
__device__ int    g_idx[NPTS * KNN];
__device__ float  g_partials[NBLK_LOSS];
__device__ float  g_wsum;

// 5-bit -> every-3rd-bit spread for morton interleave
__device__ __forceinline__ unsigned mpart5(unsigned x) {
    x &= 31u;
    x = (x | (x << 8)) & 0x100Fu;
    x = (x | (x << 4)) & 0x10C3u;
    x = (x | (x << 2)) & 0x1249u;
    return x;
}

// ---------------------------------------------------------------------------
__global__ void zero_kernel() {
    int i = blockIdx.x * 256 + threadIdx.x;
    if (i < NCELLS) g_cnt[i] = 0;
}

__global__ void count_kernel(const float* __restrict__ pc) {
    int i = blockIdx.x * 256 + threadIdx.x;
    float x = pc[i * 3 + 0], y = pc[i * 3 + 1], z = pc[i * 3 + 2];
    int cx = min(31, max(0, (int)floorf((x + 5.0f) * 3.2f)));
    int cy = min(31, max(0, (int)floorf((y + 5.0f) * 3.2f)));
    int cz = min(31, max(0, (int)floorf((z + 5.0f) * 3.2f)));
    int key = (int)(mpart5(cx) | (mpart5(cy) << 1) | (mpart5(cz) << 2));
    g_key[i] = key;
    atomicAdd(&g_cnt[key], 1);
}

// single block, 1024 threads: exclusive scan of 32768 counts
__global__ void scan_kernel() {
    __shared__ int s[1024];
    int t = threadIdx.x;
    int base = t * 32;
    int loc[32];
    int sum = 0;
#pragma unroll
    for (int k = 0; k < 32; k++) { loc[k] = g_cnt[base + k]; sum += loc[k]; }
    s[t] = sum;
    __syncthreads();
    for (int off = 1; off < 1024; off <<= 1) {
        int v = (t >= off) ? s[t - off] : 0;
        __syncthreads();
        s[t] += v;
        __syncthreads();
    }
    int run = s[t] - sum;
#pragma unroll
    for (int k = 0; k < 32; k++) { g_cur[base + k] = run; run += loc[k]; }
}

__global__ void scatter_kernel(const float* __restrict__ pc) {
    int i = blockIdx.x * 256 + threadIdx.x;
    int pos = atomicAdd(&g_cur[g_key[i]], 1);
    g_sorted[pos] = make_float4(pc[i * 3 + 0], pc[i * 3 + 1], pc[i * 3 + 2],
                                __int_as_float(i));
}

// one warp per tile: shfl min/max reduce
__global__ void bbox_kernel() {
    const int tile = blockIdx.x;
    const int lane = threadIdx.x;
    float lx = 3e38f, ly = 3e38f, lz = 3e38f;
    float hx = -3e38f, hy = -3e38f, hz = -3e38f;
    const float4* p = g_sorted + tile * TPT;
#pragma unroll
    for (int j = 0; j < TPT / 32; j++) {
        float4 c = p[lane + j * 32];
        lx = fminf(lx, c.x); hx = fmaxf(hx, c.x);
        ly = fminf(ly, c.y); hy = fmaxf(hy, c.y);
        lz = fminf(lz, c.z); hz = fmaxf(hz, c.z);
    }
#pragma unroll
    for (int off = 16; off > 0; off >>= 1) {
        lx = fminf(lx, __shfl_xor_sync(0xFFFFFFFFu, lx, off));
        ly = fminf(ly, __shfl_xor_sync(0xFFFFFFFFu, ly, off));
        lz = fminf(lz, __shfl_xor_sync(0xFFFFFFFFu, lz, off));
        hx = fmaxf(hx, __shfl_xor_sync(0xFFFFFFFFu, hx, off));
        hy = fmaxf(hy, __shfl_xor_sync(0xFFFFFFFFu, hy, off));
        hz = fmaxf(hz, __shfl_xor_sync(0xFFFFFFFFu, hz, off));
    }
    if (lane == 0) {
        g_blo[tile] = make_float4(lx, ly, lz, 0.0f);
        g_bhi[tile] = make_float4(hx, hy, hz, 0.0f);
    }
}

// ---------------------------------------------------------------------------
// Pruned kNN, 4 threads/query, smem tile staging.
// Block = 64 co-located sorted queries x 4 candidate partitions.
// Tiles visited in expanding morton order; block votes on bbox need; needed
// tiles staged to smem once and scanned by all partitions.
// Threshold for pruning = min over the 4 partition lanes of their local
// 16th-best (a provable upper bound on the combined 16th-best).
// Lexicographic (d2, idx) ordering everywhere -> deterministic, lax.top_k ties.
// ---------------------------------------------------------------------------
__global__ __launch_bounds__(QPB * PARTS) void knn_kernel() {
    __shared__ __align__(16) float4 s4[TPT];       // staged candidate tile
    __shared__ float md[QPB * (PARTS * KNN + 1)];  // merge: pitch 65
    __shared__ int   mi[QPB * (PARTS * KNN + 1)];

    const int t    = threadIdx.x;
    const int ql   = t >> 2;          // local query 0..63
    const int part = t & 3;           // partition 0..3
    const int gid  = blockIdx.x * QPB + ql;   // sorted query index
    const int tile0 = blockIdx.x >> 1;        // block spans half a tile

    const float4 q = g_sorted[gid];

    float d[KNN];
    int   id[KNN];
#pragma unroll
    for (int k = 0; k < KNN; k++) { d[k] = 3.0e38f; id[k] = 0x7FFFFFFF; }

    for (int s = 0; s < 2 * NTILES; s++) {
        int half = (s + 1) >> 1;
        int ti = (s & 1) ? (tile0 - half) : (tile0 + half);
        bool inrange = ((unsigned)ti < NTILES);

        bool need = false;
        if (inrange) {
            // combined-16th upper bound across the 4 partition lanes
            float thr = d[KNN - 1];
            thr = fminf(thr, __shfl_xor_sync(0xFFFFFFFFu, thr, 1));
            thr = fminf(thr, __shfl_xor_sync(0xFFFFFFFFu, thr, 2));

            float4 lo = g_blo[ti];
            float4 hi = g_bhi[ti];
            float ddx = fmaxf(fmaxf(lo.x - q.x, q.x - hi.x), 0.0f);
            float ddy = fmaxf(fmaxf(lo.y - q.y, q.y - hi.y), 0.0f);
            float ddz = fmaxf(fmaxf(lo.z - q.z, q.z - hi.z), 0.0f);
            float mind2 = fmaf(ddx, ddx, fmaf(ddy, ddy, ddz * ddz));
            need = (mind2 <= thr);
        }

        if (__syncthreads_or((int)need)) {
            if (t < TPT) s4[t] = g_sorted[ti * TPT + t];
            __syncthreads();

            if (need) {
                const int ibase = ti * TPT;
#pragma unroll 4
                for (int j = part; j < TPT; j += PARTS) {
                    float4 c = s4[j];
                    float dx = q.x - c.x;
                    float dy = q.y - c.y;
                    float dz = q.z - c.z;
                    float d2 = fmaf(dx, dx, fmaf(dy, dy, dz * dz));
                    int cidx = __float_as_int(c.w);
                    if (d2 < d[KNN - 1] ||
                        (d2 == d[KNN - 1] && cidx < id[KNN - 1])) {
                        bool placed = false;
#pragma unroll
                        for (int s2 = KNN - 1; s2 > 0; --s2) {
                            if (!placed) {
                                bool mv = (d[s2 - 1] > d2) ||
                                          (d[s2 - 1] == d2 && id[s2 - 1] > cidx);
                                if (mv) { d[s2] = d[s2 - 1]; id[s2] = id[s2 - 1]; }
                                else    { d[s2] = d2; id[s2] = cidx; placed = true; }
                            }
                        }
                        if (!placed) { d[0] = d2; id[0] = cidx; }
                    }
                    (void)ibase;
                }
            }
            __syncthreads();   // protect s4 against next iteration's overwrite
        }
    }

    // dump partial sorted lists (pitch 65 -> conflict-light, once)
    const int off = ql * (PARTS * KNN + 1) + part * KNN;
#pragma unroll
    for (int k = 0; k < KNN; k++) { md[off + k] = d[k]; mi[off + k] = id[k]; }
    __syncthreads();

    if (t < QPB) {
        const int boff = t * (PARTS * KNN + 1);
        float bd[KNN];
        int   bi[KNN];
#pragma unroll
        for (int k = 0; k < KNN; k++) { bd[k] = md[boff + k]; bi[k] = mi[boff + k]; }

        for (int p = 1; p < PARTS; p++) {
            const int po = boff + p * KNN;
            for (int k = 0; k < KNN; k++) {
                float v   = md[po + k];
                int   vid = mi[po + k];
                bool ins = (v < bd[KNN - 1]) ||
                           (v == bd[KNN - 1] && vid < bi[KNN - 1]);
                if (!ins) break;   // sorted sublist -> rest can't insert either
                bool placed = false;
#pragma unroll
                for (int s2 = KNN - 1; s2 > 0; --s2) {
                    if (!placed) {
                        bool mv = (bd[s2 - 1] > v) ||
                                  (bd[s2 - 1] == v && bi[s2 - 1] > vid);
                        if (mv) { bd[s2] = bd[s2 - 1]; bi[s2] = bi[s2 - 1]; }
                        else    { bd[s2] = v; bi[s2] = vid; placed = true; }
                    }
                }
                if (!placed) { bd[0] = v; bi[0] = vid; }
            }
        }

        // radius filter: dist > 1  <=>  d2 > 1 ; nearest (bd[0]=0) is self
        const int qq   = blockIdx.x * QPB + t;
        const float4 qv = g_sorted[qq];
        const int qidx = __float_as_int(qv.w);
        const int self = bi[0];
#pragma unroll
        for (int k = 0; k < KNN; k++)
            g_idx[qidx * KNN + k] = (bd[k] > 1.0f) ? self : bi[k];
    }
}

// ---------------------------------------------------------------------------
__global__ void wsum_kernel(const float* __restrict__ w) {
    __shared__ float red[256];
    float a = 0.0f;
    for (int i = threadIdx.x; i < NPTS; i += 256) a += w[i];
    red[threadIdx.x] = a;
    __syncthreads();
    for (int st = 128; st > 0; st >>= 1) {
        if (threadIdx.x < st) red[threadIdx.x] += red[threadIdx.x + st];
        __syncthreads();
    }
    if (threadIdx.x == 0) g_wsum = red[0];
}

__global__ __launch_bounds__(256) void loss_kernel(const float* __restrict__ flow,
                                                   const float* __restrict__ w) {
    const int gid = blockIdx.x * 256 + threadIdx.x;  // 0 .. SEQ*NPTS-1
    const int s   = gid / NPTS;
    const int i   = gid - s * NPTS;
    const float* f = flow + (size_t)s * NPTS * 3;

    const float fx = f[i * 3 + 0];
    const float fy = f[i * 3 + 1];
    const float fz = f[i * 3 + 2];

    float acc = 0.0f;
#pragma unroll
    for (int k = 0; k < KNN; k++) {
        int j = g_idx[i * KNN + k];
        float dx = fx - f[j * 3 + 0];
        float dy = fy - f[j * 3 + 1];
        float dz = fz - f[j * 3 + 2];
        float sq = dx * dx;
        sq = fmaf(dy, dy, sq);
        sq = fmaf(dz, dz, sq);
        acc += (sq > 0.0f) ? sqrtf(sq) : 0.0f;
    }
    float val = w[i] * (acc * (1.0f / KNN));

    __shared__ float red[256];
    red[threadIdx.x] = val;
    __syncthreads();
    for (int st = 128; st > 0; st >>= 1) {
        if (threadIdx.x < st) red[threadIdx.x] += red[threadIdx.x + st];
        __syncthreads();
    }
    if (threadIdx.x == 0) g_partials[blockIdx.x] = red[0];
}

__global__ void final_kernel(float* __restrict__ out) {
    __shared__ float red[512];
    red[threadIdx.x] = g_partials[threadIdx.x];
    __syncthreads();
    for (int st = 256; st > 0; st >>= 1) {
        if (threadIdx.x < st) red[threadIdx.x] += red[threadIdx.x + st];
        __syncthreads();
    }
    if (threadIdx.x == 0) {
        float tot = red[0];
        float ws  = g_wsum;
        float ls  = (ws > 0.0f) ? (tot / ws) : tot;
        out[0] = ls * (1.0f / SEQ);
    }
}

// ---------------------------------------------------------------------------
extern "C" void kernel_launch(void* const* d_in, const int* in_sizes, int n_in,
                              void* d_out, int out_size) {
    const float* pc   = (const float*)d_in[0];  // (1, 16384, 3)
    const float* flow = (const float*)d_in[1];  // (8, 16384, 3)
    const float* w    = (const float*)d_in[2];  // (16384,)
    float* out = (float*)d_out;

    zero_kernel<<<NCELLS / 256, 256>>>();
    count_kernel<<<NPTS / 256, 256>>>(pc);
    scan_kernel<<<1, 1024>>>();
    scatter_kernel<<<NPTS / 256, 256>>>(pc);
    bbox_kernel<<<NTILES, 32>>>();
    knn_kernel<<<NPTS / QPB, QPB * PARTS>>>();
    wsum_kernel<<<1, 256>>>(w);
    loss_kernel<<<NBLK_LOSS, 256>>>(flow, w);
    final_kernel<<<1, 512>>>(out);
}